// round 1
// baseline (speedup 1.0000x reference)
#include <cuda_runtime.h>

// Problem constants (fixed shapes for this problem)
#define N_MAX 100000
#define D 64

// Scratch (allocation-free rule: __device__ globals)
__device__ float g_h[N_MAX * D];      // transformed features of current layer
__device__ float g_x1[N_MAX * D];     // layer-1 output
__device__ float g_accum[N_MAX * D];  // weighted aggregation buffer
__device__ float g_as[N_MAX];         // alpha_src per node
__device__ float g_ad[N_MAX];         // alpha_dst per node
__device__ float g_denom[N_MAX];      // softmax denominator per node

// ---------------------------------------------------------------------------
// GEMM: h = x @ W  (N x 64 @ 64 x 64), fused epilogue:
//   g_as = h . a_src, g_ad = h . a_dst, and zero accum/denom for edge pass.
// Block: 64 threads, 64 rows. Each thread computes an 8x8 register tile.
// ---------------------------------------------------------------------------
__global__ void gat_gemm_kernel(const float* __restrict__ xin,
                                const float* __restrict__ W,
                                const float* __restrict__ a_src,
                                const float* __restrict__ a_dst,
                                int N)
{
    constexpr int RB = 64;
    __shared__ float xs[RB][D + 1];   // +1 pad: conflict-free strided reads
    __shared__ float ws[D][D + 4];    // +4 pad: aligned float4 rows, spread banks

    const float* x = xin ? xin : g_x1;
    const int tid = threadIdx.x;            // 0..63
    const int r0 = blockIdx.x * RB;

    // Load W (64x64) into smem, padded rows
    #pragma unroll
    for (int it = 0; it < 16; it++) {
        int i = it * 64 + tid;               // 0..1023 float4 index
        int k = i >> 4, c4 = (i & 15) << 2;
        float4 v = ((const float4*)W)[i];
        ws[k][c4 + 0] = v.x; ws[k][c4 + 1] = v.y;
        ws[k][c4 + 2] = v.z; ws[k][c4 + 3] = v.w;
    }
    // Load x tile (64x64) + zero accum slice for the upcoming edge pass
    #pragma unroll
    for (int it = 0; it < 16; it++) {
        int i = it * 64 + tid;
        int r = i >> 4, c4 = (i & 15) << 2;
        int gr = r0 + r;
        float4 v = make_float4(0.f, 0.f, 0.f, 0.f);
        if (gr < N) v = ((const float4*)x)[gr * 16 + (i & 15)];
        xs[r][c4 + 0] = v.x; xs[r][c4 + 1] = v.y;
        xs[r][c4 + 2] = v.z; xs[r][c4 + 3] = v.w;
        int idx4 = r0 * 16 + i;              // contiguous accum float4s for this block
        if (idx4 < N * 16)
            ((float4*)g_accum)[idx4] = make_float4(0.f, 0.f, 0.f, 0.f);
    }
    if (r0 + tid < N) g_denom[r0 + tid] = 0.f;
    __syncthreads();

    const int rg = tid >> 3, cg = tid & 7;
    const int rbase = rg * 8, cbase = cg * 8;

    float acc[8][8];
    #pragma unroll
    for (int r = 0; r < 8; r++)
        #pragma unroll
        for (int c = 0; c < 8; c++) acc[r][c] = 0.f;

    #pragma unroll
    for (int k = 0; k < D; k++) {
        float4 w0 = *(const float4*)&ws[k][cbase];
        float4 w1 = *(const float4*)&ws[k][cbase + 4];
        #pragma unroll
        for (int r = 0; r < 8; r++) {
            float xv = xs[rbase + r][k];
            acc[r][0] += xv * w0.x; acc[r][1] += xv * w0.y;
            acc[r][2] += xv * w0.z; acc[r][3] += xv * w0.w;
            acc[r][4] += xv * w1.x; acc[r][5] += xv * w1.y;
            acc[r][6] += xv * w1.z; acc[r][7] += xv * w1.w;
        }
    }

    // Epilogue: store h, reduce h.a_src / h.a_dst across the 8 col-group lanes
    float asr[8], adr[8];
    #pragma unroll
    for (int c = 0; c < 8; c++) {
        asr[c] = __ldg(&a_src[cbase + c]);
        adr[c] = __ldg(&a_dst[cbase + c]);
    }
    #pragma unroll
    for (int r = 0; r < 8; r++) {
        int gr = r0 + rbase + r;
        float ps = 0.f, pd = 0.f;
        #pragma unroll
        for (int c = 0; c < 8; c++) {
            ps += acc[r][c] * asr[c];
            pd += acc[r][c] * adr[c];
        }
        #pragma unroll
        for (int off = 4; off > 0; off >>= 1) {
            ps += __shfl_down_sync(0xffffffffu, ps, off, 8);
            pd += __shfl_down_sync(0xffffffffu, pd, off, 8);
        }
        if (gr < N) {
            ((float4*)g_h)[gr * 16 + (cbase >> 2)] =
                make_float4(acc[r][0], acc[r][1], acc[r][2], acc[r][3]);
            ((float4*)g_h)[gr * 16 + (cbase >> 2) + 1] =
                make_float4(acc[r][4], acc[r][5], acc[r][6], acc[r][7]);
            if (cg == 0) { g_as[gr] = ps; g_ad[gr] = pd; }
        }
    }
}

// ---------------------------------------------------------------------------
// Edge pass: one pass does softmax numerator + denominator + aggregation.
//   ee = exp(leaky_relu(as[src] + ad[dst]))
//   denom[dst] += ee                 (scalar atomic, lane 0 of 16)
//   accum[dst][:] += ee * h[src][:]  (16x red.global.add.v4.f32)
// 16 threads per edge -> each h-row gather is a fully-coalesced 256B read.
// Edge ids >= E are the implicit self-loops (src=dst=i-E).
// ---------------------------------------------------------------------------
__global__ void gat_edge_kernel(const int* __restrict__ src,
                                const int* __restrict__ dst,
                                int E, int N)
{
    int gt = blockIdx.x * blockDim.x + threadIdx.x;
    int e = gt >> 4;
    int t = gt & 15;
    int tot = E + N;
    if (e >= tot) return;

    int s, d;
    if (e < E) { s = __ldg(&src[e]); d = __ldg(&dst[e]); }
    else       { s = e - E; d = s; }

    float lg = __ldg(&g_as[s]) + __ldg(&g_ad[d]);
    lg = lg > 0.f ? lg : 0.2f * lg;
    float ee = __expf(lg);

    if (t == 0) atomicAdd(&g_denom[d], ee);

    float4 hv = __ldg(((const float4*)g_h) + s * 16 + t);
    float4* outp = ((float4*)g_accum) + d * 16 + t;
    asm volatile("red.global.add.v4.f32 [%0], {%1, %2, %3, %4};"
                 :: "l"(outp), "f"(ee * hv.x), "f"(ee * hv.y),
                    "f"(ee * hv.z), "f"(ee * hv.w)
                 : "memory");
}

// ---------------------------------------------------------------------------
// Finalize: out[n][c] = accum[n][c] / denom[n] + b[c]  (+ ELU for layer 1)
// One thread per float4. out == nullptr -> write layer-1 buffer g_x1.
// ---------------------------------------------------------------------------
__global__ void gat_finalize_kernel(const float* __restrict__ b,
                                    float* __restrict__ out,
                                    int N, int apply_elu)
{
    int i = blockIdx.x * blockDim.x + threadIdx.x;   // float4 index
    if (i >= N * 16) return;
    int n = i >> 4;
    float inv = 1.0f / g_denom[n];
    float4 v = ((const float4*)g_accum)[i];
    float4 bb = __ldg(((const float4*)b) + (i & 15));
    float o0 = v.x * inv + bb.x;
    float o1 = v.y * inv + bb.y;
    float o2 = v.z * inv + bb.z;
    float o3 = v.w * inv + bb.w;
    if (apply_elu) {
        o0 = o0 > 0.f ? o0 : expm1f(o0);
        o1 = o1 > 0.f ? o1 : expm1f(o1);
        o2 = o2 > 0.f ? o2 : expm1f(o2);
        o3 = o3 > 0.f ? o3 : expm1f(o3);
    }
    float* dstp = out ? out : g_x1;
    ((float4*)dstp)[i] = make_float4(o0, o1, o2, o3);
}

// ---------------------------------------------------------------------------
extern "C" void kernel_launch(void* const* d_in, const int* in_sizes, int n_in,
                              void* d_out, int out_size)
{
    const int*   edge = (const int*)d_in[0];     // [2, E] int32
    const float* emb  = (const float*)d_in[1];   // [N, 64]
    const float* W1   = (const float*)d_in[2];
    const float* a1s  = (const float*)d_in[3];
    const float* a1d  = (const float*)d_in[4];
    const float* b1   = (const float*)d_in[5];
    const float* W2   = (const float*)d_in[6];
    const float* a2s  = (const float*)d_in[7];
    const float* a2d  = (const float*)d_in[8];
    const float* b2   = (const float*)d_in[9];
    float* out = (float*)d_out;

    const int E = in_sizes[0] / 2;
    const int N = in_sizes[1] / D;
    const int* src = edge;
    const int* dst = edge + E;

    const int gemm_blocks = (N + 63) / 64;
    const int edge_threads = (E + N) * 16;
    const int edge_blocks = (edge_threads + 255) / 256;
    const int fin_blocks = (N * 16 + 255) / 256;

    // Layer 1
    gat_gemm_kernel<<<gemm_blocks, 64>>>(emb, W1, a1s, a1d, N);
    gat_edge_kernel<<<edge_blocks, 256>>>(src, dst, E, N);
    gat_finalize_kernel<<<fin_blocks, 256>>>(b1, nullptr, N, 1);

    // Layer 2
    gat_gemm_kernel<<<gemm_blocks, 64>>>(nullptr, W2, a2s, a2d, N);
    gat_edge_kernel<<<edge_blocks, 256>>>(src, dst, E, N);
    gat_finalize_kernel<<<fin_blocks, 256>>>(b2, out, N, 0);
}

// round 2
// speedup vs baseline: 1.6366x; 1.6366x over previous
#include <cuda_runtime.h>

#define N_MAX 100000
#define E_MAX 1600000
#define D 64

// Scratch (__device__ globals; allocation-free rule)
__device__ float g_h[N_MAX * D];      // transformed features of current layer
__device__ float g_x1[N_MAX * D];     // layer-1 output
__device__ float g_as[N_MAX];         // alpha_src per node
__device__ float g_ad[N_MAX];         // alpha_dst per node
__device__ int   g_cnt[N_MAX];        // per-dst in-degree (excl. self-loop)
__device__ int   g_rowstart[N_MAX];   // CSR row offsets (exclusive scan)
__device__ int   g_cursor[N_MAX];     // scatter cursors; == row_end after scatter
__device__ int   g_bsum[128];         // scan block sums
__device__ int   g_csrsrc[E_MAX];     // src ids grouped by dst

// ---------------------------------------------------------------------------
// CSR build: zero -> histogram -> scan (2-level) -> scatter
// ---------------------------------------------------------------------------
__global__ void k_zero_cnt(int N)
{
    int i = blockIdx.x * blockDim.x + threadIdx.x;
    if (i < N) g_cnt[i] = 0;
}

__global__ void k_hist(const int* __restrict__ dst, int E)
{
    int e = blockIdx.x * blockDim.x + threadIdx.x;
    if (e < E) atomicAdd(&g_cnt[dst[e]], 1);
}

__global__ void k_scan1(int N)   // per-block (1024) exclusive scan of g_cnt
{
    __shared__ int tmp[1024];
    int tid = threadIdx.x;
    int g = blockIdx.x * 1024 + tid;
    int v = (g < N) ? g_cnt[g] : 0;
    tmp[tid] = v;
    __syncthreads();
    #pragma unroll
    for (int off = 1; off < 1024; off <<= 1) {
        int t = (tid >= off) ? tmp[tid - off] : 0;
        __syncthreads();
        tmp[tid] += t;
        __syncthreads();
    }
    if (g < N) g_rowstart[g] = tmp[tid] - v;   // exclusive within block
    if (tid == 1023) g_bsum[blockIdx.x] = tmp[1023];
}

__global__ void k_scan2(int nb)  // tiny sequential scan of block sums
{
    if (threadIdx.x == 0 && blockIdx.x == 0) {
        int run = 0;
        for (int i = 0; i < nb; i++) { int v = g_bsum[i]; g_bsum[i] = run; run += v; }
    }
}

__global__ void k_scan3(int N)   // add block offsets; init cursors
{
    int g = blockIdx.x * 1024 + threadIdx.x;
    if (g < N) {
        int rs = g_rowstart[g] + g_bsum[blockIdx.x];
        g_rowstart[g] = rs;
        g_cursor[g] = rs;
    }
}

__global__ void k_scatter(const int* __restrict__ src,
                          const int* __restrict__ dst, int E)
{
    int e = blockIdx.x * blockDim.x + threadIdx.x;
    if (e < E) {
        int d = dst[e];
        int p = atomicAdd(&g_cursor[d], 1);
        g_csrsrc[p] = src[e];
    }
}

// ---------------------------------------------------------------------------
// GEMM: h = x @ W  (N x 64 @ 64 x 64), fused epilogue computing
// g_as = h . a_src, g_ad = h . a_dst.  64 threads/block, 8x8 tile/thread.
// ---------------------------------------------------------------------------
__global__ void gat_gemm_kernel(const float* __restrict__ xin,
                                const float* __restrict__ W,
                                const float* __restrict__ a_src,
                                const float* __restrict__ a_dst,
                                int N)
{
    constexpr int RB = 64;
    __shared__ float xs[RB][D + 1];
    __shared__ float ws[D][D + 4];

    const float* x = xin ? xin : g_x1;
    const int tid = threadIdx.x;            // 0..63
    const int r0 = blockIdx.x * RB;

    #pragma unroll
    for (int it = 0; it < 16; it++) {
        int i = it * 64 + tid;
        int k = i >> 4, c4 = (i & 15) << 2;
        float4 v = ((const float4*)W)[i];
        ws[k][c4 + 0] = v.x; ws[k][c4 + 1] = v.y;
        ws[k][c4 + 2] = v.z; ws[k][c4 + 3] = v.w;
    }
    #pragma unroll
    for (int it = 0; it < 16; it++) {
        int i = it * 64 + tid;
        int r = i >> 4, c4 = (i & 15) << 2;
        int gr = r0 + r;
        float4 v = make_float4(0.f, 0.f, 0.f, 0.f);
        if (gr < N) v = ((const float4*)x)[gr * 16 + (i & 15)];
        xs[r][c4 + 0] = v.x; xs[r][c4 + 1] = v.y;
        xs[r][c4 + 2] = v.z; xs[r][c4 + 3] = v.w;
    }
    __syncthreads();

    const int rg = tid >> 3, cg = tid & 7;
    const int rbase = rg * 8, cbase = cg * 8;

    float acc[8][8];
    #pragma unroll
    for (int r = 0; r < 8; r++)
        #pragma unroll
        for (int c = 0; c < 8; c++) acc[r][c] = 0.f;

    #pragma unroll
    for (int k = 0; k < D; k++) {
        float4 w0 = *(const float4*)&ws[k][cbase];
        float4 w1 = *(const float4*)&ws[k][cbase + 4];
        #pragma unroll
        for (int r = 0; r < 8; r++) {
            float xv = xs[rbase + r][k];
            acc[r][0] += xv * w0.x; acc[r][1] += xv * w0.y;
            acc[r][2] += xv * w0.z; acc[r][3] += xv * w0.w;
            acc[r][4] += xv * w1.x; acc[r][5] += xv * w1.y;
            acc[r][6] += xv * w1.z; acc[r][7] += xv * w1.w;
        }
    }

    float asr[8], adr[8];
    #pragma unroll
    for (int c = 0; c < 8; c++) {
        asr[c] = __ldg(&a_src[cbase + c]);
        adr[c] = __ldg(&a_dst[cbase + c]);
    }
    #pragma unroll
    for (int r = 0; r < 8; r++) {
        int gr = r0 + rbase + r;
        float ps = 0.f, pd = 0.f;
        #pragma unroll
        for (int c = 0; c < 8; c++) {
            ps += acc[r][c] * asr[c];
            pd += acc[r][c] * adr[c];
        }
        #pragma unroll
        for (int off = 4; off > 0; off >>= 1) {
            ps += __shfl_down_sync(0xffffffffu, ps, off, 8);
            pd += __shfl_down_sync(0xffffffffu, pd, off, 8);
        }
        if (gr < N) {
            ((float4*)g_h)[gr * 16 + (cbase >> 2)] =
                make_float4(acc[r][0], acc[r][1], acc[r][2], acc[r][3]);
            ((float4*)g_h)[gr * 16 + (cbase >> 2) + 1] =
                make_float4(acc[r][4], acc[r][5], acc[r][6], acc[r][7]);
            if (cg == 0) { g_as[gr] = ps; g_ad[gr] = pd; }
        }
    }
}

// ---------------------------------------------------------------------------
// Aggregation: one warp per dst node. Register accumulation; no atomics.
// Lane L owns output columns 2L, 2L+1 (one float2 = coalesced 256B/edge).
// Prefetch <=32 (src, exp-weight) per chunk into lanes, broadcast via shfl.
// Fused finalize: divide by denom, + bias, optional ELU, direct store.
// Self-loop handled explicitly (not in CSR).
// ---------------------------------------------------------------------------
__global__ void gat_aggregate_kernel(const float* __restrict__ b,
                                     float* __restrict__ out,
                                     int N, int apply_elu)
{
    int w = (blockIdx.x * blockDim.x + threadIdx.x) >> 5;
    if (w >= N) return;
    int lane = threadIdx.x & 31;

    float ad_n = __ldg(&g_ad[w]);

    // self-loop
    float lg = __ldg(&g_as[w]) + ad_n;
    lg = lg > 0.f ? lg : 0.2f * lg;
    float wself = __expf(lg);
    float2 hv = __ldg(((const float2*)g_h) + w * 32 + lane);
    float acc0 = wself * hv.x, acc1 = wself * hv.y;
    float denom = wself;

    int base = __ldg(&g_rowstart[w]);
    int end  = __ldg(&g_cursor[w]);      // cursor == row_end after scatter

    for (int c = base; c < end; c += 32) {
        int i = c + lane;
        int s = 0; float wt = 0.f;
        if (i < end) {
            s = __ldg(&g_csrsrc[i]);
            float l = __ldg(&g_as[s]) + ad_n;
            l = l > 0.f ? l : 0.2f * l;
            wt = __expf(l);
        }
        int m = min(32, end - c);
        int j = 0;
        for (; j + 4 <= m; j += 4) {
            int s0 = __shfl_sync(0xffffffffu, s, j);
            int s1 = __shfl_sync(0xffffffffu, s, j + 1);
            int s2 = __shfl_sync(0xffffffffu, s, j + 2);
            int s3 = __shfl_sync(0xffffffffu, s, j + 3);
            float w0 = __shfl_sync(0xffffffffu, wt, j);
            float w1 = __shfl_sync(0xffffffffu, wt, j + 1);
            float w2 = __shfl_sync(0xffffffffu, wt, j + 2);
            float w3 = __shfl_sync(0xffffffffu, wt, j + 3);
            float2 h0 = __ldg(((const float2*)g_h) + s0 * 32 + lane);
            float2 h1 = __ldg(((const float2*)g_h) + s1 * 32 + lane);
            float2 h2 = __ldg(((const float2*)g_h) + s2 * 32 + lane);
            float2 h3 = __ldg(((const float2*)g_h) + s3 * 32 + lane);
            acc0 += w0 * h0.x; acc1 += w0 * h0.y;
            acc0 += w1 * h1.x; acc1 += w1 * h1.y;
            acc0 += w2 * h2.x; acc1 += w2 * h2.y;
            acc0 += w3 * h3.x; acc1 += w3 * h3.y;
            denom += w0 + w1 + w2 + w3;
        }
        for (; j < m; j++) {
            int sj = __shfl_sync(0xffffffffu, s, j);
            float wj = __shfl_sync(0xffffffffu, wt, j);
            float2 hj = __ldg(((const float2*)g_h) + sj * 32 + lane);
            acc0 += wj * hj.x; acc1 += wj * hj.y;
            denom += wj;
        }
    }

    float inv = 1.0f / denom;
    float2 bb = __ldg(((const float2*)b) + lane);
    float o0 = acc0 * inv + bb.x;
    float o1 = acc1 * inv + bb.y;
    if (apply_elu) {
        o0 = o0 > 0.f ? o0 : expm1f(o0);
        o1 = o1 > 0.f ? o1 : expm1f(o1);
    }
    float* dstp = out ? out : g_x1;
    ((float2*)dstp)[w * 32 + lane] = make_float2(o0, o1);
}

// ---------------------------------------------------------------------------
extern "C" void kernel_launch(void* const* d_in, const int* in_sizes, int n_in,
                              void* d_out, int out_size)
{
    const int*   edge = (const int*)d_in[0];     // [2, E] int32
    const float* emb  = (const float*)d_in[1];   // [N, 64]
    const float* W1   = (const float*)d_in[2];
    const float* a1s  = (const float*)d_in[3];
    const float* a1d  = (const float*)d_in[4];
    const float* b1   = (const float*)d_in[5];
    const float* W2   = (const float*)d_in[6];
    const float* a2s  = (const float*)d_in[7];
    const float* a2d  = (const float*)d_in[8];
    const float* b2   = (const float*)d_in[9];
    float* out = (float*)d_out;

    const int E = in_sizes[0] / 2;
    const int N = in_sizes[1] / D;
    const int* src = edge;
    const int* dst = edge + E;

    const int gemm_blocks = (N + 63) / 64;
    const int scan_blocks = (N + 1023) / 1024;
    const int agg_blocks  = (N * 32 + 255) / 256;

    // CSR build (once; reused by both layers)
    k_zero_cnt<<<(N + 255) / 256, 256>>>(N);
    k_hist<<<(E + 255) / 256, 256>>>(dst, E);
    k_scan1<<<scan_blocks, 1024>>>(N);
    k_scan2<<<1, 32>>>(scan_blocks);
    k_scan3<<<scan_blocks, 1024>>>(N);
    k_scatter<<<(E + 255) / 256, 256>>>(src, dst, E);

    // Layer 1
    gat_gemm_kernel<<<gemm_blocks, 64>>>(emb, W1, a1s, a1d, N);
    gat_aggregate_kernel<<<agg_blocks, 256>>>(b1, nullptr, N, 1);

    // Layer 2
    gat_gemm_kernel<<<gemm_blocks, 64>>>(nullptr, W2, a2s, a2d, N);
    gat_aggregate_kernel<<<agg_blocks, 256>>>(b2, out, N, 0);
}

// round 3
// speedup vs baseline: 1.7109x; 1.0454x over previous
#include <cuda_runtime.h>
#include <cuda_fp16.h>

#define N_MAX 100000
#define E_MAX 1600000
#define D 64

// Scratch (__device__ globals; allocation-free rule)
__device__ __half g_h[N_MAX * D];     // transformed features (fp16 storage)
__device__ float  g_x1[N_MAX * D];    // layer-1 output (fp32 for GEMM2 accuracy)
__device__ float  g_as[N_MAX];        // alpha_src per node
__device__ float  g_ad[N_MAX];        // alpha_dst per node
__device__ int    g_cnt[N_MAX];       // per-dst in-degree (excl. self-loop)
__device__ int    g_rowstart[N_MAX];  // CSR row offsets
__device__ int    g_cursor[N_MAX];    // scatter cursors; == row_end after scatter
__device__ int    g_bsum[128];        // scan block sums
__device__ int    g_csrsrc[E_MAX];    // src ids grouped by dst

// ---------------------------------------------------------------------------
// CSR build: zero -> histogram -> scan (block scan + cross-block fixup) -> scatter
// ---------------------------------------------------------------------------
__global__ void k_zero_cnt(int N)
{
    int i = blockIdx.x * blockDim.x + threadIdx.x;
    if (i < N) g_cnt[i] = 0;
}

__global__ void k_hist(const int* __restrict__ dst, int E)
{
    int e = blockIdx.x * blockDim.x + threadIdx.x;
    if (e < E) atomicAdd(&g_cnt[dst[e]], 1);
}

__global__ void k_scan1(int N)   // per-block (1024) exclusive scan of g_cnt
{
    __shared__ int tmp[1024];
    int tid = threadIdx.x;
    int g = blockIdx.x * 1024 + tid;
    int v = (g < N) ? g_cnt[g] : 0;
    tmp[tid] = v;
    __syncthreads();
    #pragma unroll
    for (int off = 1; off < 1024; off <<= 1) {
        int t = (tid >= off) ? tmp[tid - off] : 0;
        __syncthreads();
        tmp[tid] += t;
        __syncthreads();
    }
    if (g < N) g_rowstart[g] = tmp[tid] - v;   // exclusive within block
    if (tid == 1023) g_bsum[blockIdx.x] = tmp[1023];
}

__global__ void k_scan3(int N)   // add prefix of block sums (computed in-block)
{
    __shared__ int s_off;
    int tid = threadIdx.x;
    if (tid < 32) {
        int p = 0;
        for (int i = tid; i < (int)blockIdx.x; i += 32) p += g_bsum[i];
        #pragma unroll
        for (int off = 16; off > 0; off >>= 1)
            p += __shfl_down_sync(0xffffffffu, p, off);
        if (tid == 0) s_off = p;
    }
    __syncthreads();
    int g = blockIdx.x * 1024 + tid;
    if (g < N) {
        int rs = g_rowstart[g] + s_off;
        g_rowstart[g] = rs;
        g_cursor[g] = rs;
    }
}

__global__ void k_scatter(const int* __restrict__ src,
                          const int* __restrict__ dst, int E)
{
    int e = blockIdx.x * blockDim.x + threadIdx.x;
    if (e < E) {
        int d = dst[e];
        int p = atomicAdd(&g_cursor[d], 1);
        g_csrsrc[p] = src[e];
    }
}

// ---------------------------------------------------------------------------
// GEMM: h = x @ W  (N x 64 @ 64 x 64). 128 threads, 128 rows/block, 8x8 tile
// per thread. Epilogue: h stored as fp16; g_as/g_ad computed in fp32.
// ---------------------------------------------------------------------------
__global__ void __launch_bounds__(128, 4)
gat_gemm_kernel(const float* __restrict__ xin,
                const float* __restrict__ W,
                const float* __restrict__ a_src,
                const float* __restrict__ a_dst,
                int N)
{
    constexpr int RB = 128;
    __shared__ float xs[RB][D + 1];
    __shared__ float ws[D][D + 4];

    const float* x = xin ? xin : g_x1;
    const int tid = threadIdx.x;            // 0..127
    const int r0 = blockIdx.x * RB;

    // Load W (64x64 = 1024 float4)
    #pragma unroll
    for (int it = 0; it < 8; it++) {
        int i = it * 128 + tid;
        int k = i >> 4, c4 = (i & 15) << 2;
        float4 v = ((const float4*)W)[i];
        ws[k][c4 + 0] = v.x; ws[k][c4 + 1] = v.y;
        ws[k][c4 + 2] = v.z; ws[k][c4 + 3] = v.w;
    }
    // Load x tile (128x64 = 2048 float4)
    #pragma unroll
    for (int it = 0; it < 16; it++) {
        int i = it * 128 + tid;
        int r = i >> 4, c4 = (i & 15) << 2;
        int gr = r0 + r;
        float4 v = make_float4(0.f, 0.f, 0.f, 0.f);
        if (gr < N) v = ((const float4*)x)[gr * 16 + (i & 15)];
        xs[r][c4 + 0] = v.x; xs[r][c4 + 1] = v.y;
        xs[r][c4 + 2] = v.z; xs[r][c4 + 3] = v.w;
    }
    __syncthreads();

    const int rg = tid >> 3, cg = tid & 7;   // 16 row-groups x 8 col-groups
    const int rbase = rg * 8, cbase = cg * 8;

    float acc[8][8];
    #pragma unroll
    for (int r = 0; r < 8; r++)
        #pragma unroll
        for (int c = 0; c < 8; c++) acc[r][c] = 0.f;

    #pragma unroll
    for (int k = 0; k < D; k++) {
        float4 w0 = *(const float4*)&ws[k][cbase];
        float4 w1 = *(const float4*)&ws[k][cbase + 4];
        #pragma unroll
        for (int r = 0; r < 8; r++) {
            float xv = xs[rbase + r][k];
            acc[r][0] += xv * w0.x; acc[r][1] += xv * w0.y;
            acc[r][2] += xv * w0.z; acc[r][3] += xv * w0.w;
            acc[r][4] += xv * w1.x; acc[r][5] += xv * w1.y;
            acc[r][6] += xv * w1.z; acc[r][7] += xv * w1.w;
        }
    }

    float asr[8], adr[8];
    #pragma unroll
    for (int c = 0; c < 8; c++) {
        asr[c] = __ldg(&a_src[cbase + c]);
        adr[c] = __ldg(&a_dst[cbase + c]);
    }
    #pragma unroll
    for (int r = 0; r < 8; r++) {
        int gr = r0 + rbase + r;
        float ps = 0.f, pd = 0.f;
        #pragma unroll
        for (int c = 0; c < 8; c++) {
            ps += acc[r][c] * asr[c];
            pd += acc[r][c] * adr[c];
        }
        #pragma unroll
        for (int off = 4; off > 0; off >>= 1) {
            ps += __shfl_down_sync(0xffffffffu, ps, off, 8);
            pd += __shfl_down_sync(0xffffffffu, pd, off, 8);
        }
        if (gr < N) {
            // pack 8 fp32 -> 8 fp16 -> one 16B store
            half2 p0 = __floats2half2_rn(acc[r][0], acc[r][1]);
            half2 p1 = __floats2half2_rn(acc[r][2], acc[r][3]);
            half2 p2 = __floats2half2_rn(acc[r][4], acc[r][5]);
            half2 p3 = __floats2half2_rn(acc[r][6], acc[r][7]);
            uint4 pk;
            pk.x = *(unsigned*)&p0; pk.y = *(unsigned*)&p1;
            pk.z = *(unsigned*)&p2; pk.w = *(unsigned*)&p3;
            ((uint4*)g_h)[gr * 8 + cg] = pk;
            if (cg == 0) { g_as[gr] = ps; g_ad[gr] = pd; }
        }
    }
}

// ---------------------------------------------------------------------------
// Aggregation: one warp per dst node; register accumulation; no atomics.
// Lane L owns cols 2L,2L+1 -> one half2 (4B) per edge = 128B/warp coalesced.
// Fused finalize (divide, bias, optional ELU).
// ---------------------------------------------------------------------------
__global__ void gat_aggregate_kernel(const float* __restrict__ b,
                                     float* __restrict__ out,
                                     int N, int apply_elu)
{
    int w = (blockIdx.x * blockDim.x + threadIdx.x) >> 5;
    if (w >= N) return;
    int lane = threadIdx.x & 31;

    float ad_n = __ldg(&g_ad[w]);

    // self-loop
    float lg = __ldg(&g_as[w]) + ad_n;
    lg = lg > 0.f ? lg : 0.2f * lg;
    float wself = __expf(lg);
    float2 hv = __half22float2(__ldg(((const half2*)g_h) + w * 32 + lane));
    float acc0 = wself * hv.x, acc1 = wself * hv.y;
    float denom = wself;

    int base = __ldg(&g_rowstart[w]);
    int end  = __ldg(&g_cursor[w]);      // cursor == row_end after scatter

    for (int c = base; c < end; c += 32) {
        int i = c + lane;
        int s = 0; float wt = 0.f;
        if (i < end) {
            s = __ldg(&g_csrsrc[i]);
            float l = __ldg(&g_as[s]) + ad_n;
            l = l > 0.f ? l : 0.2f * l;
            wt = __expf(l);
        }
        int m = min(32, end - c);
        int j = 0;
        for (; j + 4 <= m; j += 4) {
            int s0 = __shfl_sync(0xffffffffu, s, j);
            int s1 = __shfl_sync(0xffffffffu, s, j + 1);
            int s2 = __shfl_sync(0xffffffffu, s, j + 2);
            int s3 = __shfl_sync(0xffffffffu, s, j + 3);
            float w0 = __shfl_sync(0xffffffffu, wt, j);
            float w1 = __shfl_sync(0xffffffffu, wt, j + 1);
            float w2 = __shfl_sync(0xffffffffu, wt, j + 2);
            float w3 = __shfl_sync(0xffffffffu, wt, j + 3);
            float2 h0 = __half22float2(__ldg(((const half2*)g_h) + s0 * 32 + lane));
            float2 h1 = __half22float2(__ldg(((const half2*)g_h) + s1 * 32 + lane));
            float2 h2 = __half22float2(__ldg(((const half2*)g_h) + s2 * 32 + lane));
            float2 h3 = __half22float2(__ldg(((const half2*)g_h) + s3 * 32 + lane));
            acc0 += w0 * h0.x; acc1 += w0 * h0.y;
            acc0 += w1 * h1.x; acc1 += w1 * h1.y;
            acc0 += w2 * h2.x; acc1 += w2 * h2.y;
            acc0 += w3 * h3.x; acc1 += w3 * h3.y;
            denom += w0 + w1 + w2 + w3;
        }
        for (; j < m; j++) {
            int sj = __shfl_sync(0xffffffffu, s, j);
            float wj = __shfl_sync(0xffffffffu, wt, j);
            float2 hj = __half22float2(__ldg(((const half2*)g_h) + sj * 32 + lane));
            acc0 += wj * hj.x; acc1 += wj * hj.y;
            denom += wj;
        }
    }

    float inv = 1.0f / denom;
    float2 bb = __ldg(((const float2*)b) + lane);
    float o0 = acc0 * inv + bb.x;
    float o1 = acc1 * inv + bb.y;
    if (apply_elu) {
        o0 = o0 > 0.f ? o0 : expm1f(o0);
        o1 = o1 > 0.f ? o1 : expm1f(o1);
    }
    float* dstp = out ? out : g_x1;
    ((float2*)dstp)[w * 32 + lane] = make_float2(o0, o1);
}

// ---------------------------------------------------------------------------
extern "C" void kernel_launch(void* const* d_in, const int* in_sizes, int n_in,
                              void* d_out, int out_size)
{
    const int*   edge = (const int*)d_in[0];     // [2, E] int32
    const float* emb  = (const float*)d_in[1];   // [N, 64]
    const float* W1   = (const float*)d_in[2];
    const float* a1s  = (const float*)d_in[3];
    const float* a1d  = (const float*)d_in[4];
    const float* b1   = (const float*)d_in[5];
    const float* W2   = (const float*)d_in[6];
    const float* a2s  = (const float*)d_in[7];
    const float* a2d  = (const float*)d_in[8];
    const float* b2   = (const float*)d_in[9];
    float* out = (float*)d_out;

    const int E = in_sizes[0] / 2;
    const int N = in_sizes[1] / D;
    const int* src = edge;
    const int* dst = edge + E;

    const int gemm_blocks = (N + 127) / 128;
    const int scan_blocks = (N + 1023) / 1024;
    const int agg_blocks  = (N * 32 + 255) / 256;

    // CSR build (once; reused by both layers)
    k_zero_cnt<<<(N + 255) / 256, 256>>>(N);
    k_hist<<<(E + 255) / 256, 256>>>(dst, E);
    k_scan1<<<scan_blocks, 1024>>>(N);
    k_scan3<<<scan_blocks, 1024>>>(N);
    k_scatter<<<(E + 255) / 256, 256>>>(src, dst, E);

    // Layer 1
    gat_gemm_kernel<<<gemm_blocks, 128>>>(emb, W1, a1s, a1d, N);
    gat_aggregate_kernel<<<agg_blocks, 256>>>(b1, nullptr, N, 1);

    // Layer 2
    gat_gemm_kernel<<<gemm_blocks, 128>>>(nullptr, W2, a2s, a2d, N);
    gat_aggregate_kernel<<<agg_blocks, 256>>>(b2, out, N, 0);
}

// round 4
// speedup vs baseline: 1.7468x; 1.0210x over previous
#include <cuda_runtime.h>
#include <cuda_fp16.h>
#include <mma.h>

using namespace nvcuda;

#define N_MAX 100000
#define E_MAX 1600000
#define D 64

// Scratch (__device__ globals; allocation-free rule)
__device__ __half g_h[N_MAX * D];     // transformed features (fp16)
__device__ __half g_x1h[N_MAX * D];   // layer-1 output (fp16, feeds GEMM2)
__device__ float  g_as[N_MAX];        // alpha_src per node
__device__ float  g_ad[N_MAX];        // alpha_dst per node
__device__ int    g_cnt[N_MAX];       // per-dst in-degree (excl. self-loop)
__device__ int    g_rowstart[N_MAX];  // CSR row offsets
__device__ int    g_cursor[N_MAX];    // scatter cursors; == row_end after scatter
__device__ int    g_bsum[128];        // scan block sums
__device__ int    g_csrsrc[E_MAX];    // src ids grouped by dst

// ---------------------------------------------------------------------------
// CSR build: memset(g_cnt) -> histogram -> scan -> scatter
// ---------------------------------------------------------------------------
__global__ void k_hist(const int* __restrict__ dst, int E)
{
    int e = blockIdx.x * blockDim.x + threadIdx.x;
    if (e < E) atomicAdd(&g_cnt[dst[e]], 1);
}

__global__ void k_scan1(int N)   // per-block (1024) exclusive scan via warp scans
{
    __shared__ int wsum[32];
    int tid = threadIdx.x;
    int g = blockIdx.x * 1024 + tid;
    int lane = tid & 31, wid = tid >> 5;
    int v = (g < N) ? g_cnt[g] : 0;

    int x = v;                                  // inclusive warp scan
    #pragma unroll
    for (int off = 1; off < 32; off <<= 1) {
        int t = __shfl_up_sync(0xffffffffu, x, off);
        if (lane >= off) x += t;
    }
    if (lane == 31) wsum[wid] = x;
    __syncthreads();
    if (wid == 0) {                             // scan the 32 warp totals
        int y = wsum[lane];
        #pragma unroll
        for (int off = 1; off < 32; off <<= 1) {
            int t = __shfl_up_sync(0xffffffffu, y, off);
            if (lane >= off) y += t;
        }
        wsum[lane] = y;                         // inclusive
    }
    __syncthreads();
    int wpre = wid ? wsum[wid - 1] : 0;
    if (g < N) g_rowstart[g] = x - v + wpre;    // exclusive within block
    if (tid == 0) g_bsum[blockIdx.x] = wsum[31];
}

__global__ void k_scan3(int N)   // add prefix of block sums; init cursors
{
    __shared__ int s_off;
    int tid = threadIdx.x;
    if (tid < 32) {
        int p = 0;
        for (int i = tid; i < (int)blockIdx.x; i += 32) p += g_bsum[i];
        #pragma unroll
        for (int off = 16; off > 0; off >>= 1)
            p += __shfl_down_sync(0xffffffffu, p, off);
        if (tid == 0) s_off = p;
    }
    __syncthreads();
    int g = blockIdx.x * 1024 + tid;
    if (g < N) {
        int rs = g_rowstart[g] + s_off;
        g_rowstart[g] = rs;
        g_cursor[g] = rs;
    }
}

__global__ void k_scatter(const int* __restrict__ src,
                          const int* __restrict__ dst, int E)
{
    int e = blockIdx.x * blockDim.x + threadIdx.x;
    if (e < E) {
        int d = dst[e];
        int p = atomicAdd(&g_cursor[d], 1);
        g_csrsrc[p] = src[e];
    }
}

// ---------------------------------------------------------------------------
// Tensor-core GEMM: h = x @ W  (fp16 in, fp32 accum), 128 rows/block,
// 8 warps, each warp does a 16x64 slice via 4x4 wmma m16n16k16.
// Epilogue: g_as/g_ad dots in fp32, h packed to fp16.
// xf (fp32) or xh (fp16): exactly one non-null.
// ---------------------------------------------------------------------------
__global__ void __launch_bounds__(256, 3)
gat_gemm_wmma(const float* __restrict__ xf,
              const __half* __restrict__ xh,
              const float* __restrict__ W,
              const float* __restrict__ a_src,
              const float* __restrict__ a_dst,
              int N)
{
    // smem union: [xs 128x72 fp16 | ws 64x72 fp16]  then  [cs 8x16x64 fp32]
    __shared__ __align__(16) char smem_raw[32768];
    __half* xs = (__half*)smem_raw;               // [128][72]
    __half* ws = (__half*)(smem_raw + 18432);     // [64][72]
    float*  cs = (float*)smem_raw;                // [8][16][64]

    const int tid = threadIdx.x;                  // 0..255
    const int r0 = blockIdx.x * 128;
    const int warp = tid >> 5, lane = tid & 31;

    // Load W (64x64 fp32 -> fp16), 1024 float4
    #pragma unroll
    for (int it = 0; it < 4; it++) {
        int i = it * 256 + tid;
        int k = i >> 4, c4 = (i & 15) << 2;
        float4 v = ((const float4*)W)[i];
        half2* p = (half2*)&ws[k * 72 + c4];
        p[0] = __floats2half2_rn(v.x, v.y);
        p[1] = __floats2half2_rn(v.z, v.w);
    }
    // Load x tile (128x64)
    if (xf) {
        #pragma unroll
        for (int it = 0; it < 8; it++) {
            int i = it * 256 + tid;               // float4 index
            int r = i >> 4, c4 = (i & 15) << 2;
            int gr = r0 + r;
            float4 v = make_float4(0.f, 0.f, 0.f, 0.f);
            if (gr < N) v = ((const float4*)xf)[gr * 16 + (i & 15)];
            half2* p = (half2*)&xs[r * 72 + c4];
            p[0] = __floats2half2_rn(v.x, v.y);
            p[1] = __floats2half2_rn(v.z, v.w);
        }
    } else {
        #pragma unroll
        for (int it = 0; it < 4; it++) {
            int i = it * 256 + tid;               // 16B-chunk index (8 halves)
            int r = i >> 3, c8 = (i & 7) << 3;
            int gr = r0 + r;
            uint4 v = make_uint4(0u, 0u, 0u, 0u);
            if (gr < N) v = ((const uint4*)xh)[gr * 8 + (i & 7)];
            *(uint4*)&xs[r * 72 + c8] = v;
        }
    }
    __syncthreads();

    // MMA: warp covers rows [warp*16, warp*16+16), all 64 cols
    wmma::fragment<wmma::accumulator, 16, 16, 16, float> fc[4];
    #pragma unroll
    for (int n = 0; n < 4; n++) wmma::fill_fragment(fc[n], 0.0f);
    #pragma unroll
    for (int k = 0; k < 4; k++) {
        wmma::fragment<wmma::matrix_a, 16, 16, 16, __half, wmma::row_major> fa;
        wmma::load_matrix_sync(fa, &xs[(warp * 16) * 72 + k * 16], 72);
        #pragma unroll
        for (int n = 0; n < 4; n++) {
            wmma::fragment<wmma::matrix_b, 16, 16, 16, __half, wmma::row_major> fb;
            wmma::load_matrix_sync(fb, &ws[(k * 16) * 72 + n * 16], 72);
            wmma::mma_sync(fc[n], fa, fb, fc[n]);
        }
    }
    __syncthreads();   // xs/ws reads done chip-wide -> safe to overlay cs

    float* csw = cs + warp * 16 * 64;
    #pragma unroll
    for (int n = 0; n < 4; n++)
        wmma::store_matrix_sync(csw + n * 16, fc[n], 64, wmma::mem_row_major);
    __syncwarp();

    // Epilogue: lane owns cols 2*lane, 2*lane+1 of each of the 16 rows
    float2 as2 = __ldg(((const float2*)a_src) + lane);
    float2 ad2 = __ldg(((const float2*)a_dst) + lane);
    #pragma unroll
    for (int r = 0; r < 16; r++) {
        float2 hv = *(const float2*)&csw[r * 64 + lane * 2];
        float ps = hv.x * as2.x + hv.y * as2.y;
        float pd = hv.x * ad2.x + hv.y * ad2.y;
        #pragma unroll
        for (int off = 16; off > 0; off >>= 1) {
            ps += __shfl_down_sync(0xffffffffu, ps, off);
            pd += __shfl_down_sync(0xffffffffu, pd, off);
        }
        int gr = r0 + warp * 16 + r;
        if (gr < N) {
            ((half2*)g_h)[gr * 32 + lane] = __floats2half2_rn(hv.x, hv.y);
            if (lane == 0) { g_as[gr] = ps; g_ad[gr] = pd; }
        }
    }
}

// ---------------------------------------------------------------------------
// Aggregation: warp per dst node; register accumulation; no atomics, no shfl.
// csrsrc/g_as loads are warp-uniform (1 broadcast transaction each).
// Fused finalize (divide, bias, optional ELU). Output fp16 (layer1) or fp32.
// ---------------------------------------------------------------------------
__global__ void __launch_bounds__(256)
gat_aggregate_kernel(const float* __restrict__ b,
                     float* __restrict__ outf,
                     __half* __restrict__ outh,
                     int N, int apply_elu)
{
    int w = (blockIdx.x * blockDim.x + threadIdx.x) >> 5;
    if (w >= N) return;
    int lane = threadIdx.x & 31;

    const half2* hh = (const half2*)g_h;
    float ad_n = __ldg(&g_ad[w]);

    // self-loop
    float lg = __ldg(&g_as[w]) + ad_n;
    lg = lg > 0.f ? lg : 0.2f * lg;
    float wself = __expf(lg);
    float2 hv = __half22float2(__ldg(hh + w * 32 + lane));
    float acc0 = wself * hv.x, acc1 = wself * hv.y;
    float denom = wself;

    int j   = __ldg(&g_rowstart[w]);
    int end = __ldg(&g_cursor[w]);       // cursor == row_end after scatter

    for (; j + 4 <= end; j += 4) {
        int s0 = __ldg(&g_csrsrc[j]);
        int s1 = __ldg(&g_csrsrc[j + 1]);
        int s2 = __ldg(&g_csrsrc[j + 2]);
        int s3 = __ldg(&g_csrsrc[j + 3]);
        float l0 = __ldg(&g_as[s0]) + ad_n;
        float l1 = __ldg(&g_as[s1]) + ad_n;
        float l2 = __ldg(&g_as[s2]) + ad_n;
        float l3 = __ldg(&g_as[s3]) + ad_n;
        l0 = l0 > 0.f ? l0 : 0.2f * l0;
        l1 = l1 > 0.f ? l1 : 0.2f * l1;
        l2 = l2 > 0.f ? l2 : 0.2f * l2;
        l3 = l3 > 0.f ? l3 : 0.2f * l3;
        float w0 = __expf(l0), w1 = __expf(l1);
        float w2 = __expf(l2), w3 = __expf(l3);
        float2 h0 = __half22float2(__ldg(hh + s0 * 32 + lane));
        float2 h1 = __half22float2(__ldg(hh + s1 * 32 + lane));
        float2 h2 = __half22float2(__ldg(hh + s2 * 32 + lane));
        float2 h3 = __half22float2(__ldg(hh + s3 * 32 + lane));
        acc0 += w0 * h0.x; acc1 += w0 * h0.y;
        acc0 += w1 * h1.x; acc1 += w1 * h1.y;
        acc0 += w2 * h2.x; acc1 += w2 * h2.y;
        acc0 += w3 * h3.x; acc1 += w3 * h3.y;
        denom += w0 + w1 + w2 + w3;
    }
    for (; j < end; j++) {
        int s = __ldg(&g_csrsrc[j]);
        float l = __ldg(&g_as[s]) + ad_n;
        l = l > 0.f ? l : 0.2f * l;
        float wj = __expf(l);
        float2 hj = __half22float2(__ldg(hh + s * 32 + lane));
        acc0 += wj * hj.x; acc1 += wj * hj.y;
        denom += wj;
    }

    float inv = 1.0f / denom;
    float2 bb = __ldg(((const float2*)b) + lane);
    float o0 = acc0 * inv + bb.x;
    float o1 = acc1 * inv + bb.y;
    if (apply_elu) {
        o0 = o0 > 0.f ? o0 : expm1f(o0);
        o1 = o1 > 0.f ? o1 : expm1f(o1);
    }
    if (outh) ((half2*)outh)[w * 32 + lane] = __floats2half2_rn(o0, o1);
    else      ((float2*)outf)[w * 32 + lane] = make_float2(o0, o1);
}

// ---------------------------------------------------------------------------
extern "C" void kernel_launch(void* const* d_in, const int* in_sizes, int n_in,
                              void* d_out, int out_size)
{
    const int*   edge = (const int*)d_in[0];     // [2, E] int32
    const float* emb  = (const float*)d_in[1];   // [N, 64]
    const float* W1   = (const float*)d_in[2];
    const float* a1s  = (const float*)d_in[3];
    const float* a1d  = (const float*)d_in[4];
    const float* b1   = (const float*)d_in[5];
    const float* W2   = (const float*)d_in[6];
    const float* a2s  = (const float*)d_in[7];
    const float* a2d  = (const float*)d_in[8];
    const float* b2   = (const float*)d_in[9];
    float* out = (float*)d_out;

    const int E = in_sizes[0] / 2;
    const int N = in_sizes[1] / D;
    const int* src = edge;
    const int* dst = edge + E;

    const int gemm_blocks = (N + 127) / 128;
    const int scan_blocks = (N + 1023) / 1024;
    const int agg_blocks  = (N * 32 + 255) / 256;

    // CSR build (once; reused by both layers)
    void* cntp = nullptr;
    cudaGetSymbolAddress(&cntp, g_cnt);
    cudaMemsetAsync(cntp, 0, N * sizeof(int));
    k_hist<<<(E + 255) / 256, 256>>>(dst, E);
    k_scan1<<<scan_blocks, 1024>>>(N);
    k_scan3<<<scan_blocks, 1024>>>(N);
    k_scatter<<<(E + 255) / 256, 256>>>(src, dst, E);

    __half* x1h = nullptr;
    cudaGetSymbolAddress((void**)&x1h, g_x1h);

    // Layer 1
    gat_gemm_wmma<<<gemm_blocks, 256>>>(emb, nullptr, W1, a1s, a1d, N);
    gat_aggregate_kernel<<<agg_blocks, 256>>>(b1, nullptr, x1h, N, 1);

    // Layer 2
    gat_gemm_wmma<<<gemm_blocks, 256>>>(nullptr, x1h, W2, a2s, a2d, N);
    gat_aggregate_kernel<<<agg_blocks, 256>>>(b2, out, nullptr, N, 0);
}

// round 5
// speedup vs baseline: 1.8754x; 1.0736x over previous
#include <cuda_runtime.h>
#include <cuda_fp16.h>
#include <mma.h>

using namespace nvcuda;

#define N_MAX 100000
#define E_MAX 1600000
#define D 64

// Scratch (__device__ globals; allocation-free rule)
__device__ __half g_h[N_MAX * D];     // transformed features (fp16)
__device__ __half g_x1h[N_MAX * D];   // layer-1 output (fp16, feeds GEMM2)
__device__ float  g_as[N_MAX];        // alpha_src per node
__device__ float  g_ad[N_MAX];        // alpha_dst per node
__device__ int    g_cnt[N_MAX];       // per-dst in-degree (excl. self-loop)
__device__ int    g_rowstart[N_MAX];  // CSR row offsets
__device__ int    g_bsum[128];        // scan block sums
__device__ int    g_rank[E_MAX];      // edge rank within its dst bucket
__device__ int    g_csrsrc[E_MAX];    // src ids grouped by dst

// ---------------------------------------------------------------------------
// CSR build: memset(g_cnt) -> hist(+rank) -> scan -> atomic-free scatter
// ---------------------------------------------------------------------------
__global__ void k_hist(const int* __restrict__ dst, int E)
{
    int e = blockIdx.x * blockDim.x + threadIdx.x;
    if (e < E) g_rank[e] = atomicAdd(&g_cnt[dst[e]], 1);
}

__global__ void k_scan1(int N)   // per-block (1024) exclusive scan via warp scans
{
    __shared__ int wsum[32];
    int tid = threadIdx.x;
    int g = blockIdx.x * 1024 + tid;
    int lane = tid & 31, wid = tid >> 5;
    int v = (g < N) ? g_cnt[g] : 0;

    int x = v;                                  // inclusive warp scan
    #pragma unroll
    for (int off = 1; off < 32; off <<= 1) {
        int t = __shfl_up_sync(0xffffffffu, x, off);
        if (lane >= off) x += t;
    }
    if (lane == 31) wsum[wid] = x;
    __syncthreads();
    if (wid == 0) {                             // scan the 32 warp totals
        int y = wsum[lane];
        #pragma unroll
        for (int off = 1; off < 32; off <<= 1) {
            int t = __shfl_up_sync(0xffffffffu, y, off);
            if (lane >= off) y += t;
        }
        wsum[lane] = y;                         // inclusive
    }
    __syncthreads();
    int wpre = wid ? wsum[wid - 1] : 0;
    if (g < N) g_rowstart[g] = x - v + wpre;    // exclusive within block
    if (tid == 0) g_bsum[blockIdx.x] = wsum[31];
}

__global__ void k_scan3(int N)   // add prefix of block sums
{
    __shared__ int s_off;
    int tid = threadIdx.x;
    if (tid < 32) {
        int p = 0;
        for (int i = tid; i < (int)blockIdx.x; i += 32) p += g_bsum[i];
        #pragma unroll
        for (int off = 16; off > 0; off >>= 1)
            p += __shfl_down_sync(0xffffffffu, p, off);
        if (tid == 0) s_off = p;
    }
    __syncthreads();
    int g = blockIdx.x * 1024 + tid;
    if (g < N) g_rowstart[g] += s_off;
}

__global__ void k_scatter(const int* __restrict__ src,
                          const int* __restrict__ dst, int E)
{
    int e = blockIdx.x * blockDim.x + threadIdx.x;
    if (e < E) {
        int p = __ldg(&g_rowstart[dst[e]]) + g_rank[e];
        g_csrsrc[p] = src[e];
    }
}

// ---------------------------------------------------------------------------
// Tensor-core GEMM: h = x @ W  (fp16 in, fp32 accum), 128 rows/block,
// 8 warps, each warp does a 16x64 slice via 4x4 wmma m16n16k16.
// Epilogue: g_as/g_ad dots in fp32, h packed to fp16.
// ---------------------------------------------------------------------------
__global__ void __launch_bounds__(256, 3)
gat_gemm_wmma(const float* __restrict__ xf,
              const __half* __restrict__ xh,
              const float* __restrict__ W,
              const float* __restrict__ a_src,
              const float* __restrict__ a_dst,
              int N)
{
    __shared__ __align__(16) char smem_raw[32768];
    __half* xs = (__half*)smem_raw;               // [128][72]
    __half* ws = (__half*)(smem_raw + 18432);     // [64][72]
    float*  cs = (float*)smem_raw;                // [8][16][64]

    const int tid = threadIdx.x;
    const int r0 = blockIdx.x * 128;
    const int warp = tid >> 5, lane = tid & 31;

    #pragma unroll
    for (int it = 0; it < 4; it++) {
        int i = it * 256 + tid;
        int k = i >> 4, c4 = (i & 15) << 2;
        float4 v = ((const float4*)W)[i];
        half2* p = (half2*)&ws[k * 72 + c4];
        p[0] = __floats2half2_rn(v.x, v.y);
        p[1] = __floats2half2_rn(v.z, v.w);
    }
    if (xf) {
        #pragma unroll
        for (int it = 0; it < 8; it++) {
            int i = it * 256 + tid;
            int r = i >> 4, c4 = (i & 15) << 2;
            int gr = r0 + r;
            float4 v = make_float4(0.f, 0.f, 0.f, 0.f);
            if (gr < N) v = ((const float4*)xf)[gr * 16 + (i & 15)];
            half2* p = (half2*)&xs[r * 72 + c4];
            p[0] = __floats2half2_rn(v.x, v.y);
            p[1] = __floats2half2_rn(v.z, v.w);
        }
    } else {
        #pragma unroll
        for (int it = 0; it < 4; it++) {
            int i = it * 256 + tid;
            int r = i >> 3, c8 = (i & 7) << 3;
            int gr = r0 + r;
            uint4 v = make_uint4(0u, 0u, 0u, 0u);
            if (gr < N) v = ((const uint4*)xh)[gr * 8 + (i & 7)];
            *(uint4*)&xs[r * 72 + c8] = v;
        }
    }
    __syncthreads();

    wmma::fragment<wmma::accumulator, 16, 16, 16, float> fc[4];
    #pragma unroll
    for (int n = 0; n < 4; n++) wmma::fill_fragment(fc[n], 0.0f);
    #pragma unroll
    for (int k = 0; k < 4; k++) {
        wmma::fragment<wmma::matrix_a, 16, 16, 16, __half, wmma::row_major> fa;
        wmma::load_matrix_sync(fa, &xs[(warp * 16) * 72 + k * 16], 72);
        #pragma unroll
        for (int n = 0; n < 4; n++) {
            wmma::fragment<wmma::matrix_b, 16, 16, 16, __half, wmma::row_major> fb;
            wmma::load_matrix_sync(fb, &ws[(k * 16) * 72 + n * 16], 72);
            wmma::mma_sync(fc[n], fa, fb, fc[n]);
        }
    }
    __syncthreads();

    float* csw = cs + warp * 16 * 64;
    #pragma unroll
    for (int n = 0; n < 4; n++)
        wmma::store_matrix_sync(csw + n * 16, fc[n], 64, wmma::mem_row_major);
    __syncwarp();

    float2 as2 = __ldg(((const float2*)a_src) + lane);
    float2 ad2 = __ldg(((const float2*)a_dst) + lane);
    #pragma unroll
    for (int r = 0; r < 16; r++) {
        float2 hv = *(const float2*)&csw[r * 64 + lane * 2];
        float ps = hv.x * as2.x + hv.y * as2.y;
        float pd = hv.x * ad2.x + hv.y * ad2.y;
        #pragma unroll
        for (int off = 16; off > 0; off >>= 1) {
            ps += __shfl_down_sync(0xffffffffu, ps, off);
            pd += __shfl_down_sync(0xffffffffu, pd, off);
        }
        int gr = r0 + warp * 16 + r;
        if (gr < N) {
            ((half2*)g_h)[gr * 32 + lane] = __floats2half2_rn(hv.x, hv.y);
            if (lane == 0) { g_as[gr] = ps; g_ad[gr] = pd; }
        }
    }
}

// ---------------------------------------------------------------------------
// Aggregation: warp per dst node, split into 4 lane-groups of 8.
// Group g processes edge j+g; each lane loads a 16B uint4 (8 fp16 cols).
// 4 edges in flight per loop iter, ~2x fewer instructions per edge.
// Cross-group shfl_xor reduction once per node. Fused finalize.
// ---------------------------------------------------------------------------
__global__ void __launch_bounds__(256)
gat_aggregate_kernel(const float* __restrict__ b,
                     float* __restrict__ outf,
                     __half* __restrict__ outh,
                     int N, int apply_elu)
{
    int w = (blockIdx.x * blockDim.x + threadIdx.x) >> 5;
    if (w >= N) return;
    int lane = threadIdx.x & 31;
    int g = lane >> 3, q = lane & 7;     // group, slot within group

    const uint4* hh = (const uint4*)g_h; // 8 halves per uint4; row = 8 uint4
    float ad_n = __ldg(&g_ad[w]);

    float acc[8];
    #pragma unroll
    for (int i = 0; i < 8; i++) acc[i] = 0.f;
    float denom = 0.f;

    // self-loop handled by group 0 only
    if (g == 0) {
        float lg = __ldg(&g_as[w]) + ad_n;
        lg = lg > 0.f ? lg : 0.2f * lg;
        float ws_ = __expf(lg);
        uint4 hv = __ldg(hh + w * 8 + q);
        const half2* ph = (const half2*)&hv;
        #pragma unroll
        for (int i = 0; i < 4; i++) {
            float2 f = __half22float2(ph[i]);
            acc[2 * i]     += ws_ * f.x;
            acc[2 * i + 1] += ws_ * f.y;
        }
        denom = ws_;
    }

    int base = __ldg(&g_rowstart[w]);
    int end  = base + __ldg(&g_cnt[w]);

    for (int j = base; j < end; j += 4) {
        int i = j + g;
        int s = 0; float wt = 0.f;
        if (i < end) {
            s = __ldg(&g_csrsrc[i]);
            float l = __ldg(&g_as[s]) + ad_n;
            l = l > 0.f ? l : 0.2f * l;
            wt = __expf(l);
        }
        uint4 hv = __ldg(hh + s * 8 + q);    // s=0 when inactive: wt=0, harmless
        const half2* ph = (const half2*)&hv;
        #pragma unroll
        for (int i2 = 0; i2 < 4; i2++) {
            float2 f = __half22float2(ph[i2]);
            acc[2 * i2]     += wt * f.x;
            acc[2 * i2 + 1] += wt * f.y;
        }
        denom += wt;
    }

    // reduce across the 4 groups (lanes differing in bits 3,4)
    #pragma unroll
    for (int off = 8; off <= 16; off <<= 1) {
        denom += __shfl_xor_sync(0xffffffffu, denom, off);
        #pragma unroll
        for (int i = 0; i < 8; i++)
            acc[i] += __shfl_xor_sync(0xffffffffu, acc[i], off);
    }

    if (g == 0) {
        float inv = 1.0f / denom;
        float4 b0 = __ldg(((const float4*)b) + q * 2);
        float4 b1 = __ldg(((const float4*)b) + q * 2 + 1);
        float o[8];
        o[0] = acc[0] * inv + b0.x; o[1] = acc[1] * inv + b0.y;
        o[2] = acc[2] * inv + b0.z; o[3] = acc[3] * inv + b0.w;
        o[4] = acc[4] * inv + b1.x; o[5] = acc[5] * inv + b1.y;
        o[6] = acc[6] * inv + b1.z; o[7] = acc[7] * inv + b1.w;
        if (apply_elu) {
            #pragma unroll
            for (int i = 0; i < 8; i++)
                o[i] = o[i] > 0.f ? o[i] : expm1f(o[i]);
        }
        if (outh) {
            half2 p0 = __floats2half2_rn(o[0], o[1]);
            half2 p1 = __floats2half2_rn(o[2], o[3]);
            half2 p2 = __floats2half2_rn(o[4], o[5]);
            half2 p3 = __floats2half2_rn(o[6], o[7]);
            uint4 pk;
            pk.x = *(unsigned*)&p0; pk.y = *(unsigned*)&p1;
            pk.z = *(unsigned*)&p2; pk.w = *(unsigned*)&p3;
            ((uint4*)outh)[w * 8 + q] = pk;
        } else {
            ((float4*)outf)[w * 16 + q * 2]     = make_float4(o[0], o[1], o[2], o[3]);
            ((float4*)outf)[w * 16 + q * 2 + 1] = make_float4(o[4], o[5], o[6], o[7]);
        }
    }
}

// ---------------------------------------------------------------------------
extern "C" void kernel_launch(void* const* d_in, const int* in_sizes, int n_in,
                              void* d_out, int out_size)
{
    const int*   edge = (const int*)d_in[0];     // [2, E] int32
    const float* emb  = (const float*)d_in[1];   // [N, 64]
    const float* W1   = (const float*)d_in[2];
    const float* a1s  = (const float*)d_in[3];
    const float* a1d  = (const float*)d_in[4];
    const float* b1   = (const float*)d_in[5];
    const float* W2   = (const float*)d_in[6];
    const float* a2s  = (const float*)d_in[7];
    const float* a2d  = (const float*)d_in[8];
    const float* b2   = (const float*)d_in[9];
    float* out = (float*)d_out;

    const int E = in_sizes[0] / 2;
    const int N = in_sizes[1] / D;
    const int* src = edge;
    const int* dst = edge + E;

    const int gemm_blocks = (N + 127) / 128;
    const int scan_blocks = (N + 1023) / 1024;
    const int agg_blocks  = (N * 32 + 255) / 256;

    // CSR build (once; reused by both layers)
    void* cntp = nullptr;
    cudaGetSymbolAddress(&cntp, g_cnt);
    cudaMemsetAsync(cntp, 0, N * sizeof(int));
    k_hist<<<(E + 255) / 256, 256>>>(dst, E);
    k_scan1<<<scan_blocks, 1024>>>(N);
    k_scan3<<<scan_blocks, 1024>>>(N);
    k_scatter<<<(E + 255) / 256, 256>>>(src, dst, E);

    __half* x1h = nullptr;
    cudaGetSymbolAddress((void**)&x1h, g_x1h);

    // Layer 1
    gat_gemm_wmma<<<gemm_blocks, 256>>>(emb, nullptr, W1, a1s, a1d, N);
    gat_aggregate_kernel<<<agg_blocks, 256>>>(b1, nullptr, x1h, N, 1);

    // Layer 2
    gat_gemm_wmma<<<gemm_blocks, 256>>>(nullptr, x1h, W2, a2s, a2d, N);
    gat_aggregate_kernel<<<agg_blocks, 256>>>(b2, out, nullptr, N, 0);
}